// round 1
// baseline (speedup 1.0000x reference)
#include <cuda_runtime.h>
#include <cstdint>

// Problem constants (fixed by the dataset)
#define B_      8
#define D_      512
#define H_      8
#define HD_     64
#define L_NS_   64
#define L_S_    2048
#define L_TOT   2112   // L_S_ + L_NS_
#define LS_OUT  512
#define LQ_     576    // LS_OUT + L_NS_

// Scratch (allocation-free: device globals)
__device__ float g_K[B_ * L_TOT * D_];
__device__ float g_V[B_ * L_TOT * D_];
__device__ float g_Q[B_ * LQ_ * D_];
__device__ float g_A[B_ * LQ_ * D_];

// ---------------------------------------------------------------------------
// Shared-weight projection / output projection SGEMM.
// C[crow(m)][n] = sum_k A[arow(m)][k] * W[k][n] + bias[n],  K = N = 512
// MODE 0: K/V shared proj  (M = B*2048), arow/crow = b*L_TOT + t
// MODE 1: Q shared proj    (M = B*512),  arow = b*L_TOT + 1536 + t, crow = b*LQ + t
// MODE 2: output proj      (M = B*576),  arow = crow = m
// Tiles: BM=128, BN=64, BK=16; 256 threads; 8x4 micro-tile per thread.
// ---------------------------------------------------------------------------
template <int MODE>
__global__ __launch_bounds__(256)
void proj_gemm(const float* __restrict__ A, const float* __restrict__ W,
               const float* __restrict__ bias, float* __restrict__ C) {
    __shared__ float As[16][132];   // [k][m], padded
    __shared__ float Ws[16][64];    // [k][n]

    const int tid = threadIdx.x;
    const int m0 = blockIdx.x * 128;
    const int n0 = blockIdx.y * 64;
    const int tx = tid & 15;        // n dir: 16*4 = 64
    const int ty = tid >> 4;        // m dir: 16*8 = 128

    float acc[8][4];
#pragma unroll
    for (int i = 0; i < 8; ++i)
#pragma unroll
        for (int j = 0; j < 4; ++j) acc[i][j] = 0.f;

    const int wr = tid >> 4;            // k row for W load
    const int wc = (tid & 15) << 2;     // n col (float4)

    for (int k0 = 0; k0 < 512; k0 += 16) {
        // Load A tile (128x16) transposed into As[k][m]
#pragma unroll
        for (int p = 0; p < 2; ++p) {
            int t   = tid + p * 256;
            int row = t >> 2;            // 0..127
            int kk  = (t & 3) << 2;      // k offset (float4)
            int mi  = m0 + row;
            int arow;
            if (MODE == 0)      arow = (mi >> 11) * L_TOT + (mi & 2047);
            else if (MODE == 1) arow = (mi >> 9) * L_TOT + 1536 + (mi & 511);
            else                arow = mi;
            float4 v = *(const float4*)(A + (size_t)arow * D_ + k0 + kk);
            As[kk + 0][row] = v.x;
            As[kk + 1][row] = v.y;
            As[kk + 2][row] = v.z;
            As[kk + 3][row] = v.w;
        }
        // Load W tile (16x64)
        *(float4*)&Ws[wr][wc] = *(const float4*)(W + (size_t)(k0 + wr) * D_ + n0 + wc);
        __syncthreads();

#pragma unroll
        for (int k = 0; k < 16; ++k) {
            float4 a0 = *(const float4*)&As[k][ty * 8];
            float4 a1 = *(const float4*)&As[k][ty * 8 + 4];
            float4 bv = *(const float4*)&Ws[k][tx * 4];
            float a[8] = {a0.x, a0.y, a0.z, a0.w, a1.x, a1.y, a1.z, a1.w};
            float bb[4] = {bv.x, bv.y, bv.z, bv.w};
#pragma unroll
            for (int i = 0; i < 8; ++i)
#pragma unroll
                for (int j = 0; j < 4; ++j)
                    acc[i][j] += a[i] * bb[j];
        }
        __syncthreads();
    }

    // Epilogue
    float4 bv = *(const float4*)(bias + n0 + tx * 4);
#pragma unroll
    for (int i = 0; i < 8; ++i) {
        int mi = m0 + ty * 8 + i;
        int crow;
        if (MODE == 0)      crow = (mi >> 11) * L_TOT + (mi & 2047);
        else if (MODE == 1) crow = (mi >> 9) * LQ_ + (mi & 511);
        else                crow = mi;
        float4 o;
        o.x = acc[i][0] + bv.x;
        o.y = acc[i][1] + bv.y;
        o.z = acc[i][2] + bv.z;
        o.w = acc[i][3] + bv.w;
        *(float4*)(C + (size_t)crow * D_ + n0 + tx * 4) = o;
    }
}

// ---------------------------------------------------------------------------
// Per-token ("ns") projection: out[b, n, col] = sum_k x[b, L_S+n, k]*nw[n,k,col] + nb[n,col]
// Memory-bound on nw (read exactly once, coalesced). grid=(64 n, 4 col-tiles), 128 threads.
// qmode 0: out row = b*L_TOT + L_S + n   (K/V buffers)
// qmode 1: out row = b*LQ  + LS_OUT + n  (Q buffer)
// ---------------------------------------------------------------------------
__global__ __launch_bounds__(128)
void proj_ns(const float* __restrict__ x, const float* __restrict__ nw,
             const float* __restrict__ nb, float* __restrict__ out, int qmode) {
    __shared__ float xs[B_][D_];
    const int n   = blockIdx.x;
    const int tid = threadIdx.x;

    for (int t = tid; t < B_ * 128; t += 128) {
        int b  = t >> 7;
        int k4 = (t & 127) << 2;
        float4 v = *(const float4*)(x + (size_t)(b * L_TOT + L_S_ + n) * D_ + k4);
        *(float4*)&xs[b][k4] = v;
    }
    __syncthreads();

    const int col = blockIdx.y * 128 + tid;
    const float nbv = nb[n * D_ + col];
    float acc[B_];
#pragma unroll
    for (int b = 0; b < B_; ++b) acc[b] = 0.f;

    const float* wp = nw + ((size_t)n * D_) * D_ + col;
#pragma unroll 4
    for (int k = 0; k < D_; ++k) {
        float w = wp[(size_t)k * D_];
#pragma unroll
        for (int b = 0; b < B_; ++b) acc[b] += xs[b][k] * w;
    }
#pragma unroll
    for (int b = 0; b < B_; ++b) {
        int orow = qmode ? (b * LQ_ + LS_OUT + n) : (b * L_TOT + L_S_ + n);
        out[(size_t)orow * D_ + col] = acc[b] + nbv;
    }
}

// ---------------------------------------------------------------------------
// Flash attention. grid = (9 q-tiles, 8 heads, 8 batch), 256 threads.
// Q tile 64x64 (scale folded), K tiles of 64 keys. Online softmax, per-row
// stats kept redundantly in registers across the 16-lane reduction group.
// Smem: Qs[64][68] (d-major), Ks[64][68] (d-major, aliased by Ps[j][68]), Vs[64][64].
// ---------------------------------------------------------------------------
#define ATTN_SMEM ((2 * 64 * 68 + 64 * 64) * 4)

__global__ __launch_bounds__(256)
void attn_kernel(const float* __restrict__ Qg, const float* __restrict__ Kg,
                 const float* __restrict__ Vg, const int* __restrict__ pad,
                 float* __restrict__ Og) {
    extern __shared__ float sm[];
    float* Qs = sm;                  // [d][q] stride 68
    float* Ks = sm + 64 * 68;        // [d][j] stride 68; later aliased as Ps[j][q]
    float* Vs = sm + 2 * 64 * 68;    // [j][d] stride 64
    __shared__ int pads[64];

    const int tid = threadIdx.x;
    const int tx = tid & 15;         // key / d-out dir
    const int ty = tid >> 4;         // query dir
    const int qt = blockIdx.x, h = blockIdx.y, b = blockIdx.z;

    // Load + transpose Q tile, folding 1/sqrt(64) = 0.125
#pragma unroll
    for (int p = 0; p < 4; ++p) {
        int t  = tid + p * 256;
        int q  = t >> 4;
        int d4 = (t & 15) << 2;
        float4 v = *(const float4*)(Qg + (size_t)(b * LQ_ + qt * 64 + q) * D_ + h * HD_ + d4);
        Qs[(d4 + 0) * 68 + q] = v.x * 0.125f;
        Qs[(d4 + 1) * 68 + q] = v.y * 0.125f;
        Qs[(d4 + 2) * 68 + q] = v.z * 0.125f;
        Qs[(d4 + 3) * 68 + q] = v.w * 0.125f;
    }

    float m_i[4], l_i[4], Oc[4][4];
#pragma unroll
    for (int i = 0; i < 4; ++i) {
        m_i[i] = -1e30f; l_i[i] = 0.f;
#pragma unroll
        for (int j = 0; j < 4; ++j) Oc[i][j] = 0.f;
    }

    const int nkt = qt + 25;  // causal: last needed key = 64*qt+63+1536 -> tile qt+24

    for (int kt = 0; kt < nkt; ++kt) {
        __syncthreads();  // previous iter's Ps/Vs reads complete
        // Load K (transposed) and V (natural) tiles
#pragma unroll
        for (int p = 0; p < 4; ++p) {
            int t  = tid + p * 256;
            int j  = t >> 4;
            int d4 = (t & 15) << 2;
            size_t base = (size_t)(b * L_TOT + kt * 64 + j) * D_ + h * HD_ + d4;
            float4 kv = *(const float4*)(Kg + base);
            Ks[(d4 + 0) * 68 + j] = kv.x;
            Ks[(d4 + 1) * 68 + j] = kv.y;
            Ks[(d4 + 2) * 68 + j] = kv.z;
            Ks[(d4 + 3) * 68 + j] = kv.w;
            float4 vv = *(const float4*)(Vg + base);
            *(float4*)&Vs[j * 64 + d4] = vv;
        }
        if (tid < 64) {
            int kg = kt * 64 + tid;
            pads[tid] = (kg < L_S_) ? pad[b * L_S_ + kg] : 1;
        }
        __syncthreads();

        // S = Q @ K^T with mask folded into init
        float s[4][4];
#pragma unroll
        for (int i = 0; i < 4; ++i) {
            int qg = qt * 64 + ty * 4 + i;
#pragma unroll
            for (int j = 0; j < 4; ++j) {
                int kg = kt * 64 + tx * 4 + j;
                bool ok = (kg <= qg + (L_TOT - LQ_)) && (pads[tx * 4 + j] != 0);
                s[i][j] = ok ? 0.f : -1e30f;
            }
        }
#pragma unroll 8
        for (int d = 0; d < 64; ++d) {
            float4 a  = *(const float4*)&Qs[d * 68 + ty * 4];
            float4 kk = *(const float4*)&Ks[d * 68 + tx * 4];
            float av[4] = {a.x, a.y, a.z, a.w};
            float kv[4] = {kk.x, kk.y, kk.z, kk.w};
#pragma unroll
            for (int i = 0; i < 4; ++i)
#pragma unroll
                for (int j = 0; j < 4; ++j)
                    s[i][j] += av[i] * kv[j];
        }

        // Online softmax (per-row stats redundant across 16-lane group)
#pragma unroll
        for (int i = 0; i < 4; ++i) {
            float rm = fmaxf(fmaxf(s[i][0], s[i][1]), fmaxf(s[i][2], s[i][3]));
#pragma unroll
            for (int o = 8; o >= 1; o >>= 1)
                rm = fmaxf(rm, __shfl_xor_sync(0xffffffffu, rm, o));
            float mnew = fmaxf(m_i[i], rm);
            float alpha = __expf(m_i[i] - mnew);
            m_i[i] = mnew;
            float rs = 0.f;
#pragma unroll
            for (int j = 0; j < 4; ++j) {
                float p = (s[i][j] > -1e29f) ? __expf(s[i][j] - mnew) : 0.f;
                s[i][j] = p;
                rs += p;
            }
#pragma unroll
            for (int o = 8; o >= 1; o >>= 1)
                rs += __shfl_xor_sync(0xffffffffu, rs, o);
            l_i[i] = l_i[i] * alpha + rs;
#pragma unroll
            for (int j = 0; j < 4; ++j) Oc[i][j] *= alpha;
        }

        __syncthreads();  // all Ks reads done before aliased Ps writes
        float* Ps = Ks;   // [j][q] stride 68
#pragma unroll
        for (int j = 0; j < 4; ++j) {
            float4 pv = make_float4(s[0][j], s[1][j], s[2][j], s[3][j]);
            *(float4*)&Ps[(tx * 4 + j) * 68 + ty * 4] = pv;
        }
        __syncthreads();  // Ps visible

        // O += P @ V
#pragma unroll 8
        for (int j = 0; j < 64; ++j) {
            float4 pv = *(const float4*)&Ps[j * 68 + ty * 4];
            float4 vv = *(const float4*)&Vs[j * 64 + tx * 4];
            float pa[4] = {pv.x, pv.y, pv.z, pv.w};
            float va[4] = {vv.x, vv.y, vv.z, vv.w};
#pragma unroll
            for (int i = 0; i < 4; ++i)
#pragma unroll
                for (int jj = 0; jj < 4; ++jj)
                    Oc[i][jj] += pa[i] * va[jj];
        }
    }

    // Epilogue: normalize and store to g_A[b][q][h*64 + d]
#pragma unroll
    for (int i = 0; i < 4; ++i) {
        float inv = 1.f / l_i[i];
        float4 o = make_float4(Oc[i][0] * inv, Oc[i][1] * inv, Oc[i][2] * inv, Oc[i][3] * inv);
        *(float4*)(Og + (size_t)(b * LQ_ + qt * 64 + ty * 4 + i) * D_ + h * HD_ + tx * 4) = o;
    }
}

// ---------------------------------------------------------------------------
extern "C" void kernel_launch(void* const* d_in, const int* in_sizes, int n_in,
                              void* d_out, int out_size) {
    const float* x     = (const float*)d_in[0];
    const int*   pad   = (const int*)d_in[1];
    // d_in[2] = L_s (2048), d_in[3] = L_s_out (512): fixed, hardcoded
    const float* wq_sw = (const float*)d_in[4];
    const float* wq_sb = (const float*)d_in[5];
    const float* wq_nw = (const float*)d_in[6];
    const float* wq_nb = (const float*)d_in[7];
    const float* wk_sw = (const float*)d_in[8];
    const float* wk_sb = (const float*)d_in[9];
    const float* wk_nw = (const float*)d_in[10];
    const float* wk_nb = (const float*)d_in[11];
    const float* wv_sw = (const float*)d_in[12];
    const float* wv_sb = (const float*)d_in[13];
    const float* wv_nw = (const float*)d_in[14];
    const float* wv_nb = (const float*)d_in[15];
    const float* out_w = (const float*)d_in[16];
    const float* out_b = (const float*)d_in[17];
    float* out = (float*)d_out;

    float *Kp, *Vp, *Qp, *Ap;
    cudaGetSymbolAddress((void**)&Kp, g_K);
    cudaGetSymbolAddress((void**)&Vp, g_V);
    cudaGetSymbolAddress((void**)&Qp, g_Q);
    cudaGetSymbolAddress((void**)&Ap, g_A);

    cudaFuncSetAttribute(attn_kernel, cudaFuncAttributeMaxDynamicSharedMemorySize, ATTN_SMEM);

    // Projections (K, V over full L; Q over last 512 shared tokens + ns)
    proj_gemm<0><<<dim3(128, 8), 256>>>(x, wk_sw, wk_sb, Kp);
    proj_ns<<<dim3(64, 4), 128>>>(x, wk_nw, wk_nb, Kp, 0);
    proj_gemm<0><<<dim3(128, 8), 256>>>(x, wv_sw, wv_sb, Vp);
    proj_ns<<<dim3(64, 4), 128>>>(x, wv_nw, wv_nb, Vp, 0);
    proj_gemm<1><<<dim3(32, 8), 256>>>(x, wq_sw, wq_sb, Qp);
    proj_ns<<<dim3(64, 4), 128>>>(x, wq_nw, wq_nb, Qp, 1);

    // Attention
    attn_kernel<<<dim3(9, 8, 8), 256, ATTN_SMEM>>>(Qp, Kp, Vp, pad, Ap);

    // Output projection
    proj_gemm<2><<<dim3(36, 8), 256>>>(Ap, out_w, out_b, out);
}

// round 3
// speedup vs baseline: 2.6935x; 2.6935x over previous
#include <cuda_runtime.h>
#include <cstdint>

// Problem constants (fixed by the dataset)
#define B_      8
#define D_      512
#define H_      8
#define HD_     64
#define L_NS_   64
#define L_S_    2048
#define L_TOT   2112   // L_S_ + L_NS_
#define LS_OUT  512
#define LQ_     576    // LS_OUT + L_NS_

// Scratch (allocation-free: device globals)
__device__ float g_K[B_ * L_TOT * D_];
__device__ float g_V[B_ * L_TOT * D_];
__device__ float g_Q[B_ * LQ_ * D_];
__device__ float g_A[B_ * LQ_ * D_];
__device__ float g_Part[4 * 64 * B_ * D_];   // ns k-split partials (deterministic)

// ---------------------------------------------------------------------------
// mma.sync m16n8k8 tf32 helpers (baseline PTX, compiles for compute_103)
// ---------------------------------------------------------------------------
__device__ __forceinline__ uint32_t cvt_tf32(float x) {
    uint32_t u; asm("cvt.rna.tf32.f32 %0, %1;" : "=r"(u) : "f"(x)); return u;
}
__device__ __forceinline__ float uf(uint32_t u) { return __uint_as_float(u); }
__device__ __forceinline__ uint32_t fu(float f) { return __float_as_uint(f); }

__device__ __forceinline__ void mma8(float4& d, const uint32_t a[4], uint32_t b0, uint32_t b1) {
    asm volatile(
        "mma.sync.aligned.m16n8k8.row.col.f32.tf32.tf32.f32 "
        "{%0,%1,%2,%3}, {%4,%5,%6,%7}, {%8,%9}, {%0,%1,%2,%3};"
        : "+f"(d.x), "+f"(d.y), "+f"(d.z), "+f"(d.w)
        : "r"(a[0]), "r"(a[1]), "r"(a[2]), "r"(a[3]), "r"(b0), "r"(b1));
}

// ---------------------------------------------------------------------------
// Dense projection GEMM via tf32 mma.sync.
// C[crow(m)][n] = sum_k A[arow(m)][k] * W[k][n] + bias[n],  K = N = 512.
// 256 threads = 8 warps (2m x 4n), CTA tile 128x128, BK=16, warp tile 64x32.
// ---------------------------------------------------------------------------
template <int MODE> __device__ __forceinline__ int arow_of(int mi) {
    if (MODE == 0) return (mi >> 11) * L_TOT + (mi & 2047);
    if (MODE == 1) return (mi >> 9) * L_TOT + 1536 + (mi & 511);
    return mi;
}
template <int MODE> __device__ __forceinline__ int crow_of(int mi) {
    if (MODE == 0) return (mi >> 11) * L_TOT + (mi & 2047);
    if (MODE == 1) return (mi >> 9) * LQ_ + (mi & 511);
    return mi;
}

template <int MODE>
__global__ __launch_bounds__(256)
void proj_mma(const float* __restrict__ A, const float* __restrict__ W,
              const float* __restrict__ bias, float* __restrict__ C) {
    __shared__ float As[128][20];   // [m][k], tf32 patterns, stride 20 (conflict-free frags)
    __shared__ float Ws[128][21];   // [n][k], stride 21

    const int tid = threadIdx.x, lane = tid & 31;
    const int warp = tid >> 5, wm = warp >> 2, wn = warp & 3;
    const int g = lane >> 2, t4 = lane & 3;
    const int m0 = blockIdx.x * 128, n0 = blockIdx.y * 128;

    float4 acc[4][4];
#pragma unroll
    for (int i = 0; i < 4; ++i)
#pragma unroll
        for (int j = 0; j < 4; ++j) acc[i][j] = make_float4(0.f, 0.f, 0.f, 0.f);

    const int arow = tid >> 2;              // 0..63
    const int akq  = (tid & 3) * 4;         // k offset (float4)
    const int ar0  = arow_of<MODE>(m0 + arow);
    const int ar1  = arow_of<MODE>(m0 + 64 + arow);
    const int wn_  = tid & 127;
    const int wk_  = tid >> 7;              // 0 or 1

    // Prefetch first tile into registers
    float4 a0r = *(const float4*)(A + (size_t)ar0 * D_ + akq);
    float4 a1r = *(const float4*)(A + (size_t)ar1 * D_ + akq);
    float wr[8];
#pragma unroll
    for (int p = 0; p < 8; ++p)
        wr[p] = W[(size_t)(wk_ + 2 * p) * D_ + n0 + wn_];

#pragma unroll 1
    for (int k0 = 0; k0 < 512; k0 += 16) {
        // STS (convert to tf32)
        {
            float4 v;
            v.x = uf(cvt_tf32(a0r.x)); v.y = uf(cvt_tf32(a0r.y));
            v.z = uf(cvt_tf32(a0r.z)); v.w = uf(cvt_tf32(a0r.w));
            *(float4*)&As[arow][akq] = v;
            v.x = uf(cvt_tf32(a1r.x)); v.y = uf(cvt_tf32(a1r.y));
            v.z = uf(cvt_tf32(a1r.z)); v.w = uf(cvt_tf32(a1r.w));
            *(float4*)&As[64 + arow][akq] = v;
#pragma unroll
            for (int p = 0; p < 8; ++p)
                Ws[wn_][wk_ + 2 * p] = uf(cvt_tf32(wr[p]));
        }
        __syncthreads();

        // Prefetch next tile
        if (k0 + 16 < 512) {
            a0r = *(const float4*)(A + (size_t)ar0 * D_ + k0 + 16 + akq);
            a1r = *(const float4*)(A + (size_t)ar1 * D_ + k0 + 16 + akq);
#pragma unroll
            for (int p = 0; p < 8; ++p)
                wr[p] = W[(size_t)(k0 + 16 + wk_ + 2 * p) * D_ + n0 + wn_];
        }

        // Compute: 2 k-chunks of 8
#pragma unroll
        for (int kc = 0; kc < 2; ++kc) {
            const int kb = kc * 8;
            uint32_t af[4][4], bf[4][2];
#pragma unroll
            for (int mi = 0; mi < 4; ++mi) {
                int row = wm * 64 + mi * 16 + g;
                af[mi][0] = fu(As[row][kb + t4]);
                af[mi][1] = fu(As[row + 8][kb + t4]);
                af[mi][2] = fu(As[row][kb + t4 + 4]);
                af[mi][3] = fu(As[row + 8][kb + t4 + 4]);
            }
#pragma unroll
            for (int ni = 0; ni < 4; ++ni) {
                int col = wn * 32 + ni * 8 + g;
                bf[ni][0] = fu(Ws[col][kb + t4]);
                bf[ni][1] = fu(Ws[col][kb + t4 + 4]);
            }
#pragma unroll
            for (int mi = 0; mi < 4; ++mi)
#pragma unroll
                for (int ni = 0; ni < 4; ++ni)
                    mma8(acc[mi][ni], af[mi], bf[ni][0], bf[ni][1]);
        }
        __syncthreads();
    }

    // Epilogue
#pragma unroll
    for (int ni = 0; ni < 4; ++ni) {
        int col = n0 + wn * 32 + ni * 8 + 2 * t4;
        float2 bv = *(const float2*)(bias + col);
#pragma unroll
        for (int mi = 0; mi < 4; ++mi) {
            int r0 = crow_of<MODE>(m0 + wm * 64 + mi * 16 + g);
            int r1 = crow_of<MODE>(m0 + wm * 64 + mi * 16 + g + 8);
            float2 o0 = make_float2(acc[mi][ni].x + bv.x, acc[mi][ni].y + bv.y);
            float2 o1 = make_float2(acc[mi][ni].z + bv.x, acc[mi][ni].w + bv.y);
            *(float2*)(C + (size_t)r0 * D_ + col) = o0;
            *(float2*)(C + (size_t)r1 * D_ + col) = o1;
        }
    }
}

// ---------------------------------------------------------------------------
// ns projections: deterministic k-split x4 into g_Part, then reduce (+bias).
// ---------------------------------------------------------------------------
__global__ __launch_bounds__(128)
void proj_ns(const float* __restrict__ x, const float* __restrict__ nw,
             float* __restrict__ part) {
    __shared__ float xs[B_][128];
    const int n = blockIdx.x, ct = blockIdx.y, kz = blockIdx.z;
    const int tid = threadIdx.x;

    for (int t = tid; t < 256; t += 128) {
        int b = t >> 5;
        int k4 = (t & 31) << 2;
        *(float4*)&xs[b][k4] =
            *(const float4*)(x + (size_t)(b * L_TOT + L_S_ + n) * D_ + kz * 128 + k4);
    }
    __syncthreads();

    const int col = ct * 128 + tid;
    float acc[B_];
#pragma unroll
    for (int b = 0; b < B_; ++b) acc[b] = 0.f;

    const float* wp = nw + (size_t)n * D_ * D_ + (size_t)(kz * 128) * D_ + col;
#pragma unroll 8
    for (int k = 0; k < 128; ++k) {
        float w = wp[(size_t)k * D_];
#pragma unroll
        for (int b = 0; b < B_; ++b) acc[b] += xs[b][k] * w;
    }
#pragma unroll
    for (int b = 0; b < B_; ++b)
        part[(size_t)(((kz * 64 + n) * B_) + b) * D_ + col] = acc[b];
}

__global__ __launch_bounds__(512)
void ns_reduce(const float* __restrict__ part, const float* __restrict__ nb,
               float* __restrict__ out, int qmode) {
    const int n = blockIdx.x;
    const int col = threadIdx.x;
    const float bias = nb[n * D_ + col];
#pragma unroll
    for (int b = 0; b < B_; ++b) {
        float s = bias;
#pragma unroll
        for (int kz = 0; kz < 4; ++kz)
            s += part[(size_t)(((kz * 64 + n) * B_) + b) * D_ + col];
        int orow = qmode ? (b * LQ_ + LS_OUT + n) : (b * L_TOT + L_S_ + n);
        out[(size_t)orow * D_ + col] = s;
    }
}

// ---------------------------------------------------------------------------
// Flash attention via tf32 mma.sync. grid=(9,8,8), 128 threads (4 warps).
// Warp w owns q rows [16w, 16w+16). Q fragments register-resident.
// Smem: Qs[64][68] (aliased as Ps), Ks[64][68] tf32, Vs[64][72] tf32, padpen[64].
// ---------------------------------------------------------------------------
#define ATTN_SMEM ((64 * 68 + 64 * 68 + 64 * 72 + 64) * 4)

__global__ __launch_bounds__(128)
void attn_mma(const float* __restrict__ Qg, const float* __restrict__ Kg,
              const float* __restrict__ Vg, const int* __restrict__ pad,
              float* __restrict__ Og) {
    extern __shared__ float sm[];
    float* Qs = sm;                       // staging; aliased as Ps after frag extract
    float* Ks = sm + 64 * 68;
    float* Vs = sm + 2 * 64 * 68;
    float* padpen = sm + 2 * 64 * 68 + 64 * 72;
    float* Ps = Qs;

    const int tid = threadIdx.x, lane = tid & 31, w = tid >> 5;
    const int g = lane >> 2, t4 = lane & 3;
    const int qt = blockIdx.x, h = blockIdx.y, b = blockIdx.z;
    const int rl0 = 16 * w + g, rl1 = rl0 + 8;

    // Stage Q (fp32), then extract tf32 fragments (scale 1/8 folded)
#pragma unroll
    for (int p = 0; p < 8; ++p) {
        int idx = tid + p * 128;
        int row = idx >> 4, d4 = (idx & 15) * 4;
        *(float4*)&Qs[row * 68 + d4] =
            *(const float4*)(Qg + (size_t)(b * LQ_ + qt * 64 + row) * D_ + h * HD_ + d4);
    }
    __syncthreads();

    uint32_t qa[8][4];
#pragma unroll
    for (int kc = 0; kc < 8; ++kc) {
        qa[kc][0] = cvt_tf32(Qs[rl0 * 68 + kc * 8 + t4] * 0.125f);
        qa[kc][1] = cvt_tf32(Qs[rl1 * 68 + kc * 8 + t4] * 0.125f);
        qa[kc][2] = cvt_tf32(Qs[rl0 * 68 + kc * 8 + t4 + 4] * 0.125f);
        qa[kc][3] = cvt_tf32(Qs[rl1 * 68 + kc * 8 + t4 + 4] * 0.125f);
    }

    float4 oacc[8];
#pragma unroll
    for (int i = 0; i < 8; ++i) oacc[i] = make_float4(0.f, 0.f, 0.f, 0.f);
    float m0 = -1e30f, m1 = -1e30f, l0 = 0.f, l1 = 0.f;

    const int nkt = qt + 25;   // causal tile count
    for (int kt = 0; kt < nkt; ++kt) {
        __syncthreads();  // prior Ps/Ks/Vs reads (and initial Qs frag reads) done

        // Load K,V tiles (convert to tf32)
#pragma unroll
        for (int p = 0; p < 8; ++p) {
            int idx = tid + p * 128;
            int j = idx >> 4, d4 = (idx & 15) * 4;
            size_t base = (size_t)(b * L_TOT + kt * 64 + j) * D_ + h * HD_ + d4;
            float4 kv = *(const float4*)(Kg + base);
            float4 kc4;
            kc4.x = uf(cvt_tf32(kv.x)); kc4.y = uf(cvt_tf32(kv.y));
            kc4.z = uf(cvt_tf32(kv.z)); kc4.w = uf(cvt_tf32(kv.w));
            *(float4*)&Ks[j * 68 + d4] = kc4;
            float4 vv = *(const float4*)(Vg + base);
            float4 vc4;
            vc4.x = uf(cvt_tf32(vv.x)); vc4.y = uf(cvt_tf32(vv.y));
            vc4.z = uf(cvt_tf32(vv.z)); vc4.w = uf(cvt_tf32(vv.w));
            *(float4*)&Vs[j * 72 + d4] = vc4;
        }
        if (tid < 64) {
            int kg = kt * 64 + tid;
            padpen[tid] = (kg < L_S_) ? (pad[b * L_S_ + kg] ? 0.f : -1e30f) : 0.f;
        }
        __syncthreads();

        // S = Q K^T
        float4 sacc[8];
#pragma unroll
        for (int nt = 0; nt < 8; ++nt) sacc[nt] = make_float4(0.f, 0.f, 0.f, 0.f);
#pragma unroll
        for (int kc = 0; kc < 8; ++kc) {
#pragma unroll
            for (int nt = 0; nt < 8; ++nt) {
                uint32_t b0 = fu(Ks[(nt * 8 + g) * 68 + kc * 8 + t4]);
                uint32_t b1 = fu(Ks[(nt * 8 + g) * 68 + kc * 8 + t4 + 4]);
                mma8(sacc[nt], qa[kc], b0, b1);
            }
        }

        // Mask + online softmax
        const bool diag = (kt == qt + 24);
        float rmax0 = -1e30f, rmax1 = -1e30f;
#pragma unroll
        for (int nt = 0; nt < 8; ++nt) {
            int j0 = nt * 8 + 2 * t4, j1 = j0 + 1;
            float p0 = padpen[j0], p1 = padpen[j1];
            sacc[nt].x += p0; sacc[nt].y += p1;
            sacc[nt].z += p0; sacc[nt].w += p1;
            if (diag) {
                if (j0 > rl0) sacc[nt].x = -1e30f;
                if (j1 > rl0) sacc[nt].y = -1e30f;
                if (j0 > rl1) sacc[nt].z = -1e30f;
                if (j1 > rl1) sacc[nt].w = -1e30f;
            }
            rmax0 = fmaxf(rmax0, fmaxf(sacc[nt].x, sacc[nt].y));
            rmax1 = fmaxf(rmax1, fmaxf(sacc[nt].z, sacc[nt].w));
        }
        rmax0 = fmaxf(rmax0, __shfl_xor_sync(0xffffffffu, rmax0, 1));
        rmax0 = fmaxf(rmax0, __shfl_xor_sync(0xffffffffu, rmax0, 2));
        rmax1 = fmaxf(rmax1, __shfl_xor_sync(0xffffffffu, rmax1, 1));
        rmax1 = fmaxf(rmax1, __shfl_xor_sync(0xffffffffu, rmax1, 2));

        float mn0 = fmaxf(m0, rmax0), mn1 = fmaxf(m1, rmax1);
        float al0 = __expf(m0 - mn0), al1 = __expf(m1 - mn1);
        m0 = mn0; m1 = mn1;

        float rs0 = 0.f, rs1 = 0.f;
#pragma unroll
        for (int nt = 0; nt < 8; ++nt) {
            sacc[nt].x = __expf(sacc[nt].x - mn0); rs0 += sacc[nt].x;
            sacc[nt].y = __expf(sacc[nt].y - mn0); rs0 += sacc[nt].y;
            sacc[nt].z = __expf(sacc[nt].z - mn1); rs1 += sacc[nt].z;
            sacc[nt].w = __expf(sacc[nt].w - mn1); rs1 += sacc[nt].w;
        }
        rs0 += __shfl_xor_sync(0xffffffffu, rs0, 1);
        rs0 += __shfl_xor_sync(0xffffffffu, rs0, 2);
        rs1 += __shfl_xor_sync(0xffffffffu, rs1, 1);
        rs1 += __shfl_xor_sync(0xffffffffu, rs1, 2);
        l0 = l0 * al0 + rs0;
        l1 = l1 * al1 + rs1;
#pragma unroll
        for (int dt = 0; dt < 8; ++dt) {
            oacc[dt].x *= al0; oacc[dt].y *= al0;
            oacc[dt].z *= al1; oacc[dt].w *= al1;
        }

        // Store P (tf32) to smem
#pragma unroll
        for (int nt = 0; nt < 8; ++nt) {
            int j0 = nt * 8 + 2 * t4;
            Ps[rl0 * 68 + j0]     = uf(cvt_tf32(sacc[nt].x));
            Ps[rl0 * 68 + j0 + 1] = uf(cvt_tf32(sacc[nt].y));
            Ps[rl1 * 68 + j0]     = uf(cvt_tf32(sacc[nt].z));
            Ps[rl1 * 68 + j0 + 1] = uf(cvt_tf32(sacc[nt].w));
        }
        __syncthreads();

        // O += P V
#pragma unroll
        for (int jc = 0; jc < 8; ++jc) {
            uint32_t pa[4];
            pa[0] = fu(Ps[rl0 * 68 + jc * 8 + t4]);
            pa[1] = fu(Ps[rl1 * 68 + jc * 8 + t4]);
            pa[2] = fu(Ps[rl0 * 68 + jc * 8 + t4 + 4]);
            pa[3] = fu(Ps[rl1 * 68 + jc * 8 + t4 + 4]);
#pragma unroll
            for (int dt = 0; dt < 8; ++dt) {
                uint32_t b0 = fu(Vs[(jc * 8 + t4) * 72 + dt * 8 + g]);
                uint32_t b1 = fu(Vs[(jc * 8 + t4 + 4) * 72 + dt * 8 + g]);
                mma8(oacc[dt], pa, b0, b1);
            }
        }
    }

    // Epilogue
    float il0 = 1.f / l0, il1 = 1.f / l1;
#pragma unroll
    for (int dt = 0; dt < 8; ++dt) {
        int col = h * HD_ + dt * 8 + 2 * t4;
        size_t r0 = (size_t)(b * LQ_ + qt * 64 + rl0) * D_ + col;
        size_t r1 = (size_t)(b * LQ_ + qt * 64 + rl1) * D_ + col;
        *(float2*)(Og + r0) = make_float2(oacc[dt].x * il0, oacc[dt].y * il0);
        *(float2*)(Og + r1) = make_float2(oacc[dt].z * il1, oacc[dt].w * il1);
    }
}

// ---------------------------------------------------------------------------
extern "C" void kernel_launch(void* const* d_in, const int* in_sizes, int n_in,
                              void* d_out, int out_size) {
    const float* x     = (const float*)d_in[0];
    const int*   pad   = (const int*)d_in[1];
    const float* wq_sw = (const float*)d_in[4];
    const float* wq_sb = (const float*)d_in[5];
    const float* wq_nw = (const float*)d_in[6];
    const float* wq_nb = (const float*)d_in[7];
    const float* wk_sw = (const float*)d_in[8];
    const float* wk_sb = (const float*)d_in[9];
    const float* wk_nw = (const float*)d_in[10];
    const float* wk_nb = (const float*)d_in[11];
    const float* wv_sw = (const float*)d_in[12];
    const float* wv_sb = (const float*)d_in[13];
    const float* wv_nw = (const float*)d_in[14];
    const float* wv_nb = (const float*)d_in[15];
    const float* out_w = (const float*)d_in[16];
    const float* out_b = (const float*)d_in[17];
    float* out = (float*)d_out;

    float *Kp, *Vp, *Qp, *Ap, *Pp;
    cudaGetSymbolAddress((void**)&Kp, g_K);
    cudaGetSymbolAddress((void**)&Vp, g_V);
    cudaGetSymbolAddress((void**)&Qp, g_Q);
    cudaGetSymbolAddress((void**)&Ap, g_A);
    cudaGetSymbolAddress((void**)&Pp, g_Part);

    cudaFuncSetAttribute(attn_mma, cudaFuncAttributeMaxDynamicSharedMemorySize, ATTN_SMEM);

    // K projection
    proj_mma<0><<<dim3(128, 4), 256>>>(x, wk_sw, wk_sb, Kp);
    proj_ns<<<dim3(64, 4, 4), 128>>>(x, wk_nw, Pp);
    ns_reduce<<<64, 512>>>(Pp, wk_nb, Kp, 0);
    // V projection
    proj_mma<0><<<dim3(128, 4), 256>>>(x, wv_sw, wv_sb, Vp);
    proj_ns<<<dim3(64, 4, 4), 128>>>(x, wv_nw, Pp);
    ns_reduce<<<64, 512>>>(Pp, wv_nb, Vp, 0);
    // Q projection
    proj_mma<1><<<dim3(32, 4), 256>>>(x, wq_sw, wq_sb, Qp);
    proj_ns<<<dim3(64, 4, 4), 128>>>(x, wq_nw, Pp);
    ns_reduce<<<64, 512>>>(Pp, wq_nb, Qp, 1);

    // Attention
    attn_mma<<<dim3(9, 8, 8), 128, ATTN_SMEM>>>(Qp, Kp, Vp, pad, Ap);

    // Output projection
    proj_mma<2><<<dim3(36, 4), 256>>>(Ap, out_w, out_b, out);
}